// round 12
// baseline (speedup 1.0000x reference)
#include <cuda_runtime.h>
#include <cstdint>

// Problem constants
#define MDW   4
#define NB    2
#define NC    128
#define NH    64
#define NW    64
#define NF    16
#define NHW   4096
#define OUT1_ELEMS (NB*NF*4*NHW)        // 524288
#define WARP_ELEMS (NB*NC*NHW)          // 1048576

// cvol scratch: [b*F][uv=du*9+dv][h][w]  (42.5 MB)
__device__ float g_cvol[NB*NF*81*NHW];

typedef unsigned int u32;

static __device__ __forceinline__ u32 tf32_hi(float x) {
    u32 h; asm("cvt.rna.tf32.f32 %0, %1;" : "=r"(h) : "f"(x)); return h;
}
static __device__ __forceinline__ void mma_tf32(
    float& d0, float& d1, float& d2, float& d3,
    u32 a0, u32 a1, u32 a2, u32 a3, u32 b0, u32 b1)
{
    asm volatile(
        "mma.sync.aligned.m16n8k8.row.col.f32.tf32.tf32.f32 "
        "{%0,%1,%2,%3}, {%4,%5,%6,%7}, {%8,%9}, {%0,%1,%2,%3};"
        : "+f"(d0), "+f"(d1), "+f"(d2), "+f"(d3)
        : "r"(a0), "r"(a1), "r"(a2), "r"(a3), "r"(b0), "r"(b1));
}

// ---------------------------------------------------------------------------
// Kernel A: cost volume + projection via mma.sync tf32 (3xTF32 exact split)
// grid (dv=9, hp=32, b=2), block 256 (8 warps, warp <-> 16-px m-tile), 2 CTA/SM
// M=128 px (2 rows x 64 x), N=16 f, K=128 ch in 4 chunks of 32.
// smem (words): btab[2][16][2][64]=4096 | refs[2][64][36]=4608 | tars[2][72][36]=5184
// ---------------------------------------------------------------------------
#define CPAD 36
#define SMEM_MMA_BYTES ((4096 + 4608 + 5184) * 4)   // 55552

__global__ __launch_bounds__(256, 2) void cvol_mma_kernel(
    const float* __restrict__ ref, const float* __restrict__ tar,
    const float* __restrict__ pw)
{
    extern __shared__ float sm[];
    u32*   btab = (u32*)sm;           // [pass][kstep][nt][lane*2+j]
    float* refs = sm + 4096;          // [(r*64+x)*36 + c']
    float* tars = refs + 4608;        // [(r*72+xw)*36 + c'], xw = x+4 window

    const int dv = blockIdx.x, b = blockIdx.z;
    const int h0 = blockIdx.y * 2;
    const int tid  = threadIdx.x;
    const int wrp  = tid >> 5;
    const int lane = tid & 31;

    // ---- build B fragment table (whi pass 0, wlo pass 1) ----
    for (int i = tid; i < 4096; i += 256) {
        int j  = i & 1;
        int ln = (i >> 1) & 31;
        int nt = (i >> 6) & 1;
        int ks = (i >> 7) & 15;
        int pass = i >> 11;
        int c = ks*8 + (ln & 3) + j*4;
        int f = nt*8 + (ln >> 2);
        float w = pw[f*NC + c];
        u32 hb = tf32_hi(w);
        btab[i] = pass ? __float_as_uint(w - __uint_as_float(hb)) : hb;
    }
    // ---- zero tar window borders (xw 0..3 and 68..71) once ----
    for (int i = tid; i < 576; i += 256) {
        int c = i % 36, t = i / 36;
        int r = t >> 3, k = t & 7;
        int xw = (k < 4) ? k : 64 + k;
        tars[(r*72 + xw)*CPAD + c] = 0.f;
    }

    const int hr0 = h0 + dv - MDW;
    const bool okr[2] = { hr0 >= 0 && hr0 < NH, hr0+1 >= 0 && hr0+1 < NH };

    // warp geometry
    const int r   = wrp >> 2;                       // image row within pair
    const int xA0 = (wrp & 3)*16 + (lane >> 2);     // A row (pixel x) of a0/a2
    const int kl  = lane & 3;                        // A col low bits
    const int rb0 = (r*64 + xA0)*CPAD;
    const int rb1 = (r*64 + xA0 + 8)*CPAD;
    const int tb0 = (r*72 + xA0)*CPAD;               // + du*CPAD at use
    const int tb1 = (r*72 + xA0 + 8)*CPAD;

    float D[9][2][4];
#pragma unroll
    for (int du = 0; du < 9; du++)
#pragma unroll
        for (int nt = 0; nt < 2; nt++)
#pragma unroll
            for (int k = 0; k < 4; k++) D[du][nt][k] = 0.f;

    for (int ch = 0; ch < 4; ch++) {
        __syncthreads();     // previous chunk consumed (and init done)
        // stage refs: 32c x (2r x 64x)
        for (int i = tid; i < 1024; i += 256) {
            int c = i >> 5, q = i & 31;
            int rr = q >> 4, x4 = (q & 15)*4;
            float4 v = *(const float4*)&ref[((b*NC + ch*32 + c) << 12) + ((h0+rr) << 6) + x4];
            float* d = &refs[(rr*64 + x4)*CPAD + c];
            d[0] = v.x; d[CPAD] = v.y; d[2*CPAD] = v.z; d[3*CPAD] = v.w;
        }
        // stage tars interior (xw 4..67)
        for (int i = tid; i < 1024; i += 256) {
            int c = i >> 5, q = i & 31;
            int rr = q >> 4, x4 = (q & 15)*4;
            float4 v = make_float4(0.f, 0.f, 0.f, 0.f);
            if (okr[rr])
                v = *(const float4*)&tar[((b*NC + ch*32 + c) << 12) + ((hr0+rr) << 6) + x4];
            float* d = &tars[(rr*72 + x4 + 4)*CPAD + c];
            d[0] = v.x; d[CPAD] = v.y; d[2*CPAD] = v.z; d[3*CPAD] = v.w;
        }
        __syncthreads();

#pragma unroll
        for (int du = 0; du < 9; du++) {
#pragma unroll
            for (int ks = 0; ks < 4; ks++) {
                const int ck = ks*8 + kl;           // channel within chunk (+4 for high)
                // A production: 4 q values into mma fragment slots
                float ra0 = refs[rb0 + ck];
                float ra1 = refs[rb1 + ck];
                float ra2 = refs[rb0 + ck + 4];
                float ra3 = refs[rb1 + ck + 4];
                float ta0 = tars[tb0 + du*CPAD + ck];
                float ta1 = tars[tb1 + du*CPAD + ck];
                float ta2 = tars[tb0 + du*CPAD + ck + 4];
                float ta3 = tars[tb1 + du*CPAD + ck + 4];
                float p0 = ra0*ta0, p1 = ra1*ta1, p2 = ra2*ta2, p3 = ra3*ta3;
                float q0 = fmaxf(p0, 0.1f*p0);
                float q1 = fmaxf(p1, 0.1f*p1);
                float q2 = fmaxf(p2, 0.1f*p2);
                float q3 = fmaxf(p3, 0.1f*p3);
                u32 h0r = tf32_hi(q0), h1r = tf32_hi(q1);
                u32 h2r = tf32_hi(q2), h3r = tf32_hi(q3);
                u32 l0r = __float_as_uint(q0 - __uint_as_float(h0r));
                u32 l1r = __float_as_uint(q1 - __uint_as_float(h1r));
                u32 l2r = __float_as_uint(q2 - __uint_as_float(h2r));
                u32 l3r = __float_as_uint(q3 - __uint_as_float(h3r));
                // B fragments
                const int kg = ch*4 + ks;
                const u32* bh = &btab[(kg*2)*64 + lane*2];        // whi nt0, nt1 at +64
                const u32* bl = bh + 2048;                         // wlo
                u32 bh00 = bh[0],  bh01 = bh[1];
                u32 bh10 = bh[64], bh11 = bh[65];
                u32 bl00 = bl[0],  bl01 = bl[1];
                u32 bl10 = bl[64], bl11 = bl[65];
                // nt0
                mma_tf32(D[du][0][0], D[du][0][1], D[du][0][2], D[du][0][3],
                         h0r, h1r, h2r, h3r, bh00, bh01);
                mma_tf32(D[du][0][0], D[du][0][1], D[du][0][2], D[du][0][3],
                         l0r, l1r, l2r, l3r, bh00, bh01);
                mma_tf32(D[du][0][0], D[du][0][1], D[du][0][2], D[du][0][3],
                         h0r, h1r, h2r, h3r, bl00, bl01);
                // nt1
                mma_tf32(D[du][1][0], D[du][1][1], D[du][1][2], D[du][1][3],
                         h0r, h1r, h2r, h3r, bh10, bh11);
                mma_tf32(D[du][1][0], D[du][1][1], D[du][1][2], D[du][1][3],
                         l0r, l1r, l2r, l3r, bh10, bh11);
                mma_tf32(D[du][1][0], D[du][1][1], D[du][1][2], D[du][1][3],
                         h0r, h1r, h2r, h3r, bl10, bl11);
            }
        }
    }

    // ---- epilogue: D fragments -> g_cvol ----
    const int xout = (h0 + r)*64 + xA0;   // pixel linear index of a-row0
#pragma unroll
    for (int du = 0; du < 9; du++) {
        const int uv = du*9 + dv;
#pragma unroll
        for (int nt = 0; nt < 2; nt++) {
            const int f0 = nt*8 + (lane & 3)*2;
            float* p0 = &g_cvol[(((b*NF + f0)*81 + uv) << 12) + xout];
            float* p1 = p0 + (81 << 12);    // f0+1 plane
            p0[0] = D[du][nt][0];  p1[0] = D[du][nt][1];
            p0[8] = D[du][nt][2];  p1[8] = D[du][nt][3];
        }
    }
}

// ---------------------------------------------------------------------------
// Kernel B: flow_reg (argmax -> 7x7 mask -> masked softmax -> soft-argmax + entropies)
// ---------------------------------------------------------------------------
__global__ __launch_bounds__(256) void flowreg_kernel(float* __restrict__ out)
{
    int g = blockIdx.x * 256 + threadIdx.x;     // 0..131071
    int bf = g >> 12, pix = g & 4095;
    const float* base = g_cvol + ((bf*81) << 12) + pix;

    float v[81];
#pragma unroll
    for (int i = 0; i < 81; i++) v[i] = base[i << 12];

    float m = v[0]; int am = 0;
#pragma unroll
    for (int i = 1; i < 81; i++) if (v[i] > m) { m = v[i]; am = i; }
    int ub = am / 9, vb = am - 9*(am/9);

    float S = 0.f, T = 0.f, Sx = 0.f, Sy = 0.f, gS = 0.f, gT = 0.f;
#pragma unroll
    for (int u = 0; u < 9; u++) {
#pragma unroll
        for (int w = 0; w < 9; w++) {
            float d = v[u*9 + w] - m;
            float e = __expf(d);
            gS += e; gT += e*d;
            bool inm = (abs(u - ub) <= 3) && (abs(w - vb) <= 3);
            if (inm) {
                S += e; T += e*d;
                Sx += e * (float)(u - 4);
                Sy += e * (float)(w - 4);
            }
        }
    }
    float inv  = 1.f / S;
    float ginv = 1.f / gS;
    float outx = Sx * inv;
    float outy = Sy * inv;
    float lent = (logf(S)  - T  * inv ) * 0.25694936f;   // 1/log(49)
    float gent = (logf(gS) - gT * ginv) * 0.22756237f;   // 1/log(81)

    out[(bf*4 + 0)*NHW + pix] = outx;
    out[(bf*4 + 1)*NHW + pix] = outy;
    out[(bf*4 + 2)*NHW + pix] = lent;
    out[(bf*4 + 3)*NHW + pix] = gent;
}

// ---------------------------------------------------------------------------
// Kernel C: bilinear backward warp of tar_feat by flow (hypothesis f=0)
// ---------------------------------------------------------------------------
__global__ __launch_bounds__(256) void warp_kernel(
    const float* __restrict__ tar, float* __restrict__ out)
{
    int g = blockIdx.x * 256 + threadIdx.x;       // 0..1048575
    int x = g & 63, y = (g >> 6) & 63, c = (g >> 12) & 127, b = g >> 19;

    const float* fbase = out + b*(NF*4*NHW) + (y << 6) + x;  // bf = b*16+0, ch 0/1
    float fx = fbase[0];
    float fy = fbase[NHW];

    float px = (float)x + fx;
    float py = (float)y + fy;
    bool inb = (fabsf(2.0f*px/63.0f - 1.0f) < 1.0f) &&
               (fabsf(2.0f*py/63.0f - 1.0f) < 1.0f);

    float x0f = floorf(px), y0f = floorf(py);
    float wx = px - x0f, wy = py - y0f;
    int x0 = (int)x0f, y0 = (int)y0f;

    const float* img = tar + ((b*NC + c) << 12);
    float s = 0.f;
#pragma unroll
    for (int dy = 0; dy < 2; dy++) {
#pragma unroll
        for (int dx = 0; dx < 2; dx++) {
            int xi = x0 + dx, yi = y0 + dy;
            bool ok = (xi >= 0) && (xi < NW) && (yi >= 0) && (yi < NH);
            float wgt = (dx ? wx : 1.f - wx) * (dy ? wy : 1.f - wy);
            int xc = min(max(xi, 0), NW-1), yc = min(max(yi, 0), NH-1);
            s += img[(yc << 6) + xc] * (ok ? wgt : 0.f);
        }
    }
    out[OUT1_ELEMS + g] = s * (inb ? 1.f : 0.f);
}

// ---------------------------------------------------------------------------
extern "C" void kernel_launch(void* const* d_in, const int* in_sizes, int n_in,
                              void* d_out, int out_size)
{
    const float* ref = (const float*)d_in[0];
    const float* tar = (const float*)d_in[1];
    const float* pw  = (const float*)d_in[2];
    float* out = (float*)d_out;

    cudaFuncSetAttribute(cvol_mma_kernel,
                         cudaFuncAttributeMaxDynamicSharedMemorySize, SMEM_MMA_BYTES);

    dim3 gA(9, NH/2, NB);
    cvol_mma_kernel<<<gA, 256, SMEM_MMA_BYTES>>>(ref, tar, pw);
    flowreg_kernel<<<(NB*NF*NHW)/256, 256>>>(out);
    warp_kernel<<<WARP_ELEMS/256, 256>>>(tar, out);
}

// round 13
// speedup vs baseline: 1.0334x; 1.0334x over previous
#include <cuda_runtime.h>
#include <cstdint>

// Problem constants
#define MDW   4
#define NB    2
#define NC    128
#define NH    64
#define NW    64
#define NF    16
#define NHW   4096
#define OUT1_ELEMS (NB*NF*4*NHW)        // 524288
#define WARP_ELEMS (NB*NC*NHW)          // 1048576

// cvol scratch: [b*F][uv=du*9+dv][h][w]  (42.5 MB)
__device__ float g_cvol[NB*NF*81*NHW];

typedef unsigned int u32;

static __device__ __forceinline__ u32 tf32_hi(float x) {
    u32 h; asm("cvt.rna.tf32.f32 %0, %1;" : "=r"(h) : "f"(x)); return h;
}
static __device__ __forceinline__ void mma_tf32(
    float& d0, float& d1, float& d2, float& d3,
    u32 a0, u32 a1, u32 a2, u32 a3, u32 b0, u32 b1)
{
    asm volatile(
        "mma.sync.aligned.m16n8k8.row.col.f32.tf32.tf32.f32 "
        "{%0,%1,%2,%3}, {%4,%5,%6,%7}, {%8,%9}, {%0,%1,%2,%3};"
        : "+f"(d0), "+f"(d1), "+f"(d2), "+f"(d3)
        : "r"(a0), "r"(a1), "r"(a2), "r"(a3), "r"(b0), "r"(b1));
}

// ---------------------------------------------------------------------------
// Kernel A: cost volume + projection via mma.sync tf32 (3xTF32 exact split)
// grid (dv=9, hp=32, b=2), block 256 (8 warps, warp <-> 16-px m-tile), 2 CTA/SM
// M=128 px (2 rows x 64 x), N=16 f, K=128 ch in 4 chunks of 32.
// ks OUTER / du INNER: refs + B fragments hoisted into registers across du.
// smem (words): btab[2][16][2][64]=4096 | refs[2][64][36]=4608 | tars[2][72][36]=5184
// ---------------------------------------------------------------------------
#define CPAD 36
#define SMEM_MMA_BYTES ((4096 + 4608 + 5184) * 4)   // 55552

__global__ __launch_bounds__(256, 2) void cvol_mma_kernel(
    const float* __restrict__ ref, const float* __restrict__ tar,
    const float* __restrict__ pw)
{
    extern __shared__ float sm[];
    u32*   btab = (u32*)sm;           // [pass][kstep][nt][lane*2+j]
    float* refs = sm + 4096;          // [(r*64+x)*36 + c']
    float* tars = refs + 4608;        // [(r*72+xw)*36 + c'], xw = x+4 window

    const int dv = blockIdx.x, b = blockIdx.z;
    const int h0 = blockIdx.y * 2;
    const int tid  = threadIdx.x;
    const int wrp  = tid >> 5;
    const int lane = tid & 31;

    // ---- build B fragment table (whi pass 0, wlo pass 1) ----
    for (int i = tid; i < 4096; i += 256) {
        int j  = i & 1;
        int ln = (i >> 1) & 31;
        int nt = (i >> 6) & 1;
        int ks = (i >> 7) & 15;
        int pass = i >> 11;
        int c = ks*8 + (ln & 3) + j*4;
        int f = nt*8 + (ln >> 2);
        float w = pw[f*NC + c];
        u32 hb = tf32_hi(w);
        btab[i] = pass ? __float_as_uint(w - __uint_as_float(hb)) : hb;
    }
    // ---- zero tar window borders (xw 0..3 and 68..71) once ----
    for (int i = tid; i < 576; i += 256) {
        int c = i % 36, t = i / 36;
        int r = t >> 3, k = t & 7;
        int xw = (k < 4) ? k : 64 + k;
        tars[(r*72 + xw)*CPAD + c] = 0.f;
    }

    const int hr0 = h0 + dv - MDW;
    const bool okr[2] = { hr0 >= 0 && hr0 < NH, hr0+1 >= 0 && hr0+1 < NH };

    // warp geometry
    const int r   = wrp >> 2;                       // image row within pair
    const int xA0 = (wrp & 3)*16 + (lane >> 2);     // A row (pixel x) of a0/a2
    const int kl  = lane & 3;                        // A col low bits
    const int rb0 = (r*64 + xA0)*CPAD;
    const int rb1 = (r*64 + xA0 + 8)*CPAD;
    const int tb0 = (r*72 + xA0)*CPAD;               // + du*CPAD at use
    const int tb1 = (r*72 + xA0 + 8)*CPAD;

    float D[9][2][4];
#pragma unroll
    for (int du = 0; du < 9; du++)
#pragma unroll
        for (int nt = 0; nt < 2; nt++)
#pragma unroll
            for (int k = 0; k < 4; k++) D[du][nt][k] = 0.f;

    for (int ch = 0; ch < 4; ch++) {
        __syncthreads();     // previous chunk consumed (and init done)
        // stage refs: 32c x (2r x 64x)
        for (int i = tid; i < 1024; i += 256) {
            int c = i >> 5, q = i & 31;
            int rr = q >> 4, x4 = (q & 15)*4;
            float4 v = *(const float4*)&ref[((b*NC + ch*32 + c) << 12) + ((h0+rr) << 6) + x4];
            float* d = &refs[(rr*64 + x4)*CPAD + c];
            d[0] = v.x; d[CPAD] = v.y; d[2*CPAD] = v.z; d[3*CPAD] = v.w;
        }
        // stage tars interior (xw 4..67)
        for (int i = tid; i < 1024; i += 256) {
            int c = i >> 5, q = i & 31;
            int rr = q >> 4, x4 = (q & 15)*4;
            float4 v = make_float4(0.f, 0.f, 0.f, 0.f);
            if (okr[rr])
                v = *(const float4*)&tar[((b*NC + ch*32 + c) << 12) + ((hr0+rr) << 6) + x4];
            float* d = &tars[(rr*72 + x4 + 4)*CPAD + c];
            d[0] = v.x; d[CPAD] = v.y; d[2*CPAD] = v.z; d[3*CPAD] = v.w;
        }
        __syncthreads();

#pragma unroll
        for (int ks = 0; ks < 4; ks++) {
            const int ck = ks*8 + kl;           // channel within chunk (+4 for high)
            // du-invariant operands: hoisted into registers for the du loop
            float ra0 = refs[rb0 + ck];
            float ra1 = refs[rb1 + ck];
            float ra2 = refs[rb0 + ck + 4];
            float ra3 = refs[rb1 + ck + 4];
            const int kg = ch*4 + ks;
            const u32* bh = &btab[(kg*2)*64 + lane*2];        // whi nt0, nt1 at +64
            const u32* bl = bh + 2048;                         // wlo
            u32 bh00 = bh[0],  bh01 = bh[1];
            u32 bh10 = bh[64], bh11 = bh[65];
            u32 bl00 = bl[0],  bl01 = bl[1];
            u32 bl10 = bl[64], bl11 = bl[65];

#pragma unroll
            for (int du = 0; du < 9; du++) {
                float ta0 = tars[tb0 + du*CPAD + ck];
                float ta1 = tars[tb1 + du*CPAD + ck];
                float ta2 = tars[tb0 + du*CPAD + ck + 4];
                float ta3 = tars[tb1 + du*CPAD + ck + 4];
                float p0 = ra0*ta0, p1 = ra1*ta1, p2 = ra2*ta2, p3 = ra3*ta3;
                float q0 = fmaxf(p0, 0.1f*p0);
                float q1 = fmaxf(p1, 0.1f*p1);
                float q2 = fmaxf(p2, 0.1f*p2);
                float q3 = fmaxf(p3, 0.1f*p3);
                u32 h0r = tf32_hi(q0), h1r = tf32_hi(q1);
                u32 h2r = tf32_hi(q2), h3r = tf32_hi(q3);
                u32 l0r = __float_as_uint(q0 - __uint_as_float(h0r));
                u32 l1r = __float_as_uint(q1 - __uint_as_float(h1r));
                u32 l2r = __float_as_uint(q2 - __uint_as_float(h2r));
                u32 l3r = __float_as_uint(q3 - __uint_as_float(h3r));
                // nt0
                mma_tf32(D[du][0][0], D[du][0][1], D[du][0][2], D[du][0][3],
                         h0r, h1r, h2r, h3r, bh00, bh01);
                mma_tf32(D[du][0][0], D[du][0][1], D[du][0][2], D[du][0][3],
                         l0r, l1r, l2r, l3r, bh00, bh01);
                mma_tf32(D[du][0][0], D[du][0][1], D[du][0][2], D[du][0][3],
                         h0r, h1r, h2r, h3r, bl00, bl01);
                // nt1
                mma_tf32(D[du][1][0], D[du][1][1], D[du][1][2], D[du][1][3],
                         h0r, h1r, h2r, h3r, bh10, bh11);
                mma_tf32(D[du][1][0], D[du][1][1], D[du][1][2], D[du][1][3],
                         l0r, l1r, l2r, l3r, bh10, bh11);
                mma_tf32(D[du][1][0], D[du][1][1], D[du][1][2], D[du][1][3],
                         h0r, h1r, h2r, h3r, bl10, bl11);
            }
        }
    }

    // ---- epilogue: D fragments -> g_cvol ----
    const int xout = (h0 + r)*64 + xA0;   // pixel linear index of a-row0
#pragma unroll
    for (int du = 0; du < 9; du++) {
        const int uv = du*9 + dv;
#pragma unroll
        for (int nt = 0; nt < 2; nt++) {
            const int f0 = nt*8 + (lane & 3)*2;
            float* p0 = &g_cvol[(((b*NF + f0)*81 + uv) << 12) + xout];
            float* p1 = p0 + (81 << 12);    // f0+1 plane
            p0[0] = D[du][nt][0];  p1[0] = D[du][nt][1];
            p0[8] = D[du][nt][2];  p1[8] = D[du][nt][3];
        }
    }
}

// ---------------------------------------------------------------------------
// Kernel B: flow_reg (argmax -> 7x7 mask -> masked softmax -> soft-argmax + entropies)
// ---------------------------------------------------------------------------
__global__ __launch_bounds__(256) void flowreg_kernel(float* __restrict__ out)
{
    int g = blockIdx.x * 256 + threadIdx.x;     // 0..131071
    int bf = g >> 12, pix = g & 4095;
    const float* base = g_cvol + ((bf*81) << 12) + pix;

    float v[81];
#pragma unroll
    for (int i = 0; i < 81; i++) v[i] = base[i << 12];

    float m = v[0]; int am = 0;
#pragma unroll
    for (int i = 1; i < 81; i++) if (v[i] > m) { m = v[i]; am = i; }
    int ub = am / 9, vb = am - 9*(am/9);

    float S = 0.f, T = 0.f, Sx = 0.f, Sy = 0.f, gS = 0.f, gT = 0.f;
#pragma unroll
    for (int u = 0; u < 9; u++) {
#pragma unroll
        for (int w = 0; w < 9; w++) {
            float d = v[u*9 + w] - m;
            float e = __expf(d);
            gS += e; gT += e*d;
            bool inm = (abs(u - ub) <= 3) && (abs(w - vb) <= 3);
            if (inm) {
                S += e; T += e*d;
                Sx += e * (float)(u - 4);
                Sy += e * (float)(w - 4);
            }
        }
    }
    float inv  = 1.f / S;
    float ginv = 1.f / gS;
    float outx = Sx * inv;
    float outy = Sy * inv;
    float lent = (logf(S)  - T  * inv ) * 0.25694936f;   // 1/log(49)
    float gent = (logf(gS) - gT * ginv) * 0.22756237f;   // 1/log(81)

    out[(bf*4 + 0)*NHW + pix] = outx;
    out[(bf*4 + 1)*NHW + pix] = outy;
    out[(bf*4 + 2)*NHW + pix] = lent;
    out[(bf*4 + 3)*NHW + pix] = gent;
}

// ---------------------------------------------------------------------------
// Kernel C: bilinear backward warp of tar_feat by flow (hypothesis f=0)
// ---------------------------------------------------------------------------
__global__ __launch_bounds__(256) void warp_kernel(
    const float* __restrict__ tar, float* __restrict__ out)
{
    int g = blockIdx.x * 256 + threadIdx.x;       // 0..1048575
    int x = g & 63, y = (g >> 6) & 63, c = (g >> 12) & 127, b = g >> 19;

    const float* fbase = out + b*(NF*4*NHW) + (y << 6) + x;  // bf = b*16+0, ch 0/1
    float fx = fbase[0];
    float fy = fbase[NHW];

    float px = (float)x + fx;
    float py = (float)y + fy;
    bool inb = (fabsf(2.0f*px/63.0f - 1.0f) < 1.0f) &&
               (fabsf(2.0f*py/63.0f - 1.0f) < 1.0f);

    float x0f = floorf(px), y0f = floorf(py);
    float wx = px - x0f, wy = py - y0f;
    int x0 = (int)x0f, y0 = (int)y0f;

    const float* img = tar + ((b*NC + c) << 12);
    float s = 0.f;
#pragma unroll
    for (int dy = 0; dy < 2; dy++) {
#pragma unroll
        for (int dx = 0; dx < 2; dx++) {
            int xi = x0 + dx, yi = y0 + dy;
            bool ok = (xi >= 0) && (xi < NW) && (yi >= 0) && (yi < NH);
            float wgt = (dx ? wx : 1.f - wx) * (dy ? wy : 1.f - wy);
            int xc = min(max(xi, 0), NW-1), yc = min(max(yi, 0), NH-1);
            s += img[(yc << 6) + xc] * (ok ? wgt : 0.f);
        }
    }
    out[OUT1_ELEMS + g] = s * (inb ? 1.f : 0.f);
}

// ---------------------------------------------------------------------------
extern "C" void kernel_launch(void* const* d_in, const int* in_sizes, int n_in,
                              void* d_out, int out_size)
{
    const float* ref = (const float*)d_in[0];
    const float* tar = (const float*)d_in[1];
    const float* pw  = (const float*)d_in[2];
    float* out = (float*)d_out;

    cudaFuncSetAttribute(cvol_mma_kernel,
                         cudaFuncAttributeMaxDynamicSharedMemorySize, SMEM_MMA_BYTES);

    dim3 gA(9, NH/2, NB);
    cvol_mma_kernel<<<gA, 256, SMEM_MMA_BYTES>>>(ref, tar, pw);
    flowreg_kernel<<<(NB*NF*NHW)/256, 256>>>(out);
    warp_kernel<<<WARP_ELEMS/256, 256>>>(tar, out);
}